// round 3
// baseline (speedup 1.0000x reference)
#include <cuda_runtime.h>
#include <cuda_bf16.h>

#define NROWS 8192
#define NCOLS 32000
#define NVEC  (NCOLS / 4)   // 8000 float4 per row
#define BLK   256
#define UNROLL 8            // 8 float4 = 32 floats per thread per outer iter

// ex2.approx.f32 : single MUFU EX2, ~2^-22 rel err (far under 1e-3 budget)
__device__ __forceinline__ float ex2(float x) {
    float y;
    asm("ex2.approx.f32 %0, %1;" : "=f"(y) : "f"(x));
    return y;
}

// streaming (evict-first) 128-bit load
__device__ __forceinline__ float4 ldcs4(const float4* p) {
    return __ldcs(p);
}

__global__ void zero_out_kernel(float* out) { *out = 0.0f; }

__global__ __launch_bounds__(BLK)
void arcface_loss_kernel(const float* __restrict__ pred,
                         const int* __restrict__ target,
                         float* __restrict__ out) {
    // constants (double-accurate, truncated to f32)
    const float S     = 30.0f;
    const float K     = 30.0f * 1.4426950408889634f;   // S * log2(e): exp(S*c) = 2^(K*c)
    const float COSM  = 0.87758256189037271f;          // cos(0.5)
    const float SINM  = 0.47942553860420301f;          // sin(0.5)
    const float MM    = 0.23971276930210150f;          // sin(pi-0.5)*0.5
    const float TH    = -0.87758256189037271f;         // cos(pi-0.5)

    const int row = blockIdx.x;
    const float4* __restrict__ p4 =
        reinterpret_cast<const float4*>(pred + (size_t)row * NCOLS);

    // ---- hot loop: 8000 float4 / 256 threads.
    // Main body: batches of UNROLL*BLK float4 (8000 = 3*2048 + 1856 tail).
    float sum = 0.0f;
    int i = threadIdx.x;
    const int MAIN = (NVEC / (UNROLL * BLK)) * (UNROLL * BLK);  // 6144
    for (; i < MAIN; i += UNROLL * BLK) {
        float4 v[UNROLL];
        #pragma unroll
        for (int u = 0; u < UNROLL; u++)
            v[u] = ldcs4(p4 + i + u * BLK);          // front-batched LDG.128 x8
        #pragma unroll
        for (int u = 0; u < UNROLL; u++) {
            sum += ex2(K * fminf(1.0f, fmaxf(-1.0f, v[u].x)));
            sum += ex2(K * fminf(1.0f, fmaxf(-1.0f, v[u].y)));
            sum += ex2(K * fminf(1.0f, fmaxf(-1.0f, v[u].z)));
            sum += ex2(K * fminf(1.0f, fmaxf(-1.0f, v[u].w)));
        }
    }
    // tail: 1856 float4 remain, strided by BLK
    for (; i < NVEC; i += BLK) {
        float4 v = ldcs4(p4 + i);
        sum += ex2(K * fminf(1.0f, fmaxf(-1.0f, v.x)));
        sum += ex2(K * fminf(1.0f, fmaxf(-1.0f, v.y)));
        sum += ex2(K * fminf(1.0f, fmaxf(-1.0f, v.z)));
        sum += ex2(K * fminf(1.0f, fmaxf(-1.0f, v.w)));
    }

    // ---- block reduction ----
    __shared__ float warp_sums[BLK / 32];
    #pragma unroll
    for (int o = 16; o > 0; o >>= 1)
        sum += __shfl_xor_sync(0xffffffffu, sum, o);
    const int wid = threadIdx.x >> 5;
    const int lid = threadIdx.x & 31;
    if (lid == 0) warp_sums[wid] = sum;
    __syncthreads();

    if (threadIdx.x == 0) {
        float tot = 0.0f;
        #pragma unroll
        for (int w = 0; w < BLK / 32; w++) tot += warp_sums[w];

        // ---- target-column correction (scalar, per row) ----
        const int tgt = target[row];
        const float ct = fminf(1.0f, fmaxf(-1.0f,
                          __ldg(pred + (size_t)row * NCOLS + tgt)));
        // cos(acos(ct) + M) = ct*cosM - sqrt(1-ct^2)*sinM  (exact identity)
        const float sm = sqrtf(fmaxf(0.0f, 1.0f - ct * ct));
        float tm = ct * COSM - sm * SINM;
        tm = (ct > TH) ? tm : (ct - MM);

        // replace exp(S*ct) by exp(S*tm) in the row sum
        tot += ex2(K * tm) - ex2(K * ct);

        const float loss = logf(tot) - S * tm;
        atomicAdd(out, loss * (1.0f / (float)NROWS));
    }
}

extern "C" void kernel_launch(void* const* d_in, const int* in_sizes, int n_in,
                              void* d_out, int out_size) {
    const float* pred   = (const float*)d_in[0];
    const int*   target = (const int*)d_in[1];
    float*       out    = (float*)d_out;

    zero_out_kernel<<<1, 1>>>(out);
    arcface_loss_kernel<<<NROWS, BLK>>>(pred, target, out);
}

// round 4
// speedup vs baseline: 1.0143x; 1.0143x over previous
#include <cuda_runtime.h>
#include <cuda_bf16.h>

#define NROWS 8192
#define NCOLS 32000
#define NVEC  (NCOLS / 4)   // 8000 float4 per row
#define BLK   256

// ex2.approx.f32 : single MUFU EX2, ~2^-22 rel err (far under 1e-3 budget)
__device__ __forceinline__ float ex2(float x) {
    float y;
    asm("ex2.approx.f32 %0, %1;" : "=f"(y) : "f"(x));
    return y;
}

__global__ void zero_out_kernel(float* out) { *out = 0.0f; }

__global__ __launch_bounds__(BLK)
void arcface_loss_kernel(const float* __restrict__ pred,
                         const int* __restrict__ target,
                         float* __restrict__ out) {
    // constants (double-accurate, truncated to f32)
    const float S     = 30.0f;
    const float K     = 30.0f * 1.4426950408889634f;   // S * log2(e): exp(S*c) = 2^(K*c)
    const float COSM  = 0.87758256189037271f;          // cos(0.5)
    const float SINM  = 0.47942553860420301f;          // sin(0.5)
    const float MM    = 0.23971276930210150f;          // sin(pi-0.5)*0.5
    const float TH    = -0.87758256189037271f;         // cos(pi-0.5)

    const int row = blockIdx.x;
    const float4* __restrict__ p4 =
        reinterpret_cast<const float4*>(pred + (size_t)row * NCOLS);

    // ---- hot loop: uniform stride-BLK stream; two accumulators to break
    // the serial FADD dependency chain (lat 4) and let loads pipeline.
    float s0 = 0.0f, s1 = 0.0f;
    #pragma unroll 4
    for (int i = threadIdx.x; i < NVEC; i += BLK) {
        float4 v = p4[i];
        s0 += ex2(K * fminf(1.0f, fmaxf(-1.0f, v.x)));
        s1 += ex2(K * fminf(1.0f, fmaxf(-1.0f, v.y)));
        s0 += ex2(K * fminf(1.0f, fmaxf(-1.0f, v.z)));
        s1 += ex2(K * fminf(1.0f, fmaxf(-1.0f, v.w)));
    }
    float sum = s0 + s1;

    // ---- block reduction ----
    __shared__ float warp_sums[BLK / 32];
    #pragma unroll
    for (int o = 16; o > 0; o >>= 1)
        sum += __shfl_xor_sync(0xffffffffu, sum, o);
    const int wid = threadIdx.x >> 5;
    const int lid = threadIdx.x & 31;
    if (lid == 0) warp_sums[wid] = sum;
    __syncthreads();

    if (threadIdx.x == 0) {
        float tot = 0.0f;
        #pragma unroll
        for (int w = 0; w < BLK / 32; w++) tot += warp_sums[w];

        // ---- target-column correction (scalar, per row) ----
        const int tgt = target[row];
        const float ct = fminf(1.0f, fmaxf(-1.0f,
                          __ldg(pred + (size_t)row * NCOLS + tgt)));
        // cos(acos(ct) + M) = ct*cosM - sqrt(1-ct^2)*sinM  (exact identity)
        const float sm = sqrtf(fmaxf(0.0f, 1.0f - ct * ct));
        float tm = ct * COSM - sm * SINM;
        tm = (ct > TH) ? tm : (ct - MM);

        // replace exp(S*ct) by exp(S*tm) in the row sum
        tot += ex2(K * tm) - ex2(K * ct);

        const float loss = logf(tot) - S * tm;
        atomicAdd(out, loss * (1.0f / (float)NROWS));
    }
}

extern "C" void kernel_launch(void* const* d_in, const int* in_sizes, int n_in,
                              void* d_out, int out_size) {
    const float* pred   = (const float*)d_in[0];
    const int*   target = (const int*)d_in[1];
    float*       out    = (float*)d_out;

    zero_out_kernel<<<1, 1>>>(out);
    arcface_loss_kernel<<<NROWS, BLK>>>(pred, target, out);
}